// round 16
// baseline (speedup 1.0000x reference)
#include <cuda_runtime.h>
#include <cuda_bf16.h>
#include <math.h>
#include <stdint.h>

#define BB 64
#define NL 256
#define EE 512
#define DD 512
#define UU 512

#define NROWS_LEAF (BB*NL)   // 16384
#define NROWS_LVL  16320     // sum over levels 1..8 of B*(256>>l)

// ---- scratch (device globals; no allocation allowed) ----
__device__ float g_leaf_h[NROWS_LEAF*DD];     // fp32 leaf memories (WRITE epi + upd)
__device__ float g_levels[NROWS_LVL*DD];      // fp32 join levels (mr_kernel)
__device__ float g_part[8388608];             // split-K partials
__device__ float g_mr[NROWS_LVL];
__device__ float g_ctrl_s[BB];
__device__ float g_ctrl_T[BB];
__device__ float g_ctrl_Wh[BB*DD];
__device__ float g_attn[NROWS_LEAF];
__device__ float g_upd[NROWS_LEAF];
__device__ float g_tree_out[BB*EE];
__device__ float g_z[BB*4*UU];

// pre-split bf16 hi/lo planes: weights [n][k], activations [m][k]
__device__ __nv_bfloat16 g_wt_h[512*512],  g_wt_l[512*512];    // W_t^T
__device__ __nv_bfloat16 g_wj_h[512*1024], g_wj_l[512*1024];   // W_j^T
__device__ __nv_bfloat16 g_wh_h[512*512],  g_wh_l[512*512];    // W_h[0:512]^T
__device__ __nv_bfloat16 g_in_h[NROWS_LEAF*EE], g_in_l[NROWS_LEAF*EE];   // inputs
__device__ __nv_bfloat16 g_lf_h[NROWS_LEAF*DD], g_lf_l[NROWS_LEAF*DD];   // leaf_h
__device__ __nv_bfloat16 g_lv_h[NROWS_LVL*DD],  g_lv_l[NROWS_LVL*DD];    // levels

__constant__ int c_lvl_off[10] = {0, 0, 8192, 12288, 14336, 15360, 15872, 16128, 16256, 16320};
__constant__ int c_lvl_m[9]   = {0, 128, 64, 32, 16, 8, 4, 2, 1};

__device__ __forceinline__ float sigmoidf_(float x) { return 1.0f / (1.0f + expf(-x)); }

#define MODE_RELU  1
#define MODE_WRITE 2
#define MODE_PART  3

__device__ __forceinline__ void mma_bf16_(float* d, const uint32_t* a, const uint32_t* b) {
    asm volatile(
        "mma.sync.aligned.m16n8k16.row.col.f32.bf16.bf16.f32 "
        "{%0,%1,%2,%3}, {%4,%5,%6,%7}, {%8,%9}, {%0,%1,%2,%3};"
        : "+f"(d[0]), "+f"(d[1]), "+f"(d[2]), "+f"(d[3])
        : "r"(a[0]), "r"(a[1]), "r"(a[2]), "r"(a[3]), "r"(b[0]), "r"(b[1]));
}
__device__ __forceinline__ void ldsm4_(uint32_t* r, uint32_t saddr) {
    asm volatile("ldmatrix.sync.aligned.m8n8.x4.shared.b16 {%0,%1,%2,%3}, [%4];"
        : "=r"(r[0]), "=r"(r[1]), "=r"(r[2]), "=r"(r[3]) : "r"(saddr));
}
// hi pair: truncated bf16 of two floats packed into one word (1 PRMT)
__device__ __forceinline__ uint32_t hipair_(float a, float b) {
    return __byte_perm(__float_as_uint(a), __float_as_uint(b), 0x7632);
}
// lo pair: bf16_rn of residuals after truncation
__device__ __forceinline__ uint32_t lopair_(float a, float b) {
    float ra = a - __uint_as_float(__float_as_uint(a) & 0xffff0000u);
    float rb = b - __uint_as_float(__float_as_uint(b) & 0xffff0000u);
    uint32_t ua = (uint32_t)__bfloat16_as_ushort(__float2bfloat16_rn(ra));
    uint32_t ub = (uint32_t)__bfloat16_as_ushort(__float2bfloat16_rn(rb));
    return ua | (ub << 16);
}
#define CPA16(smem, gptr, sz) \
    asm volatile("cp.async.cg.shared.global [%0], [%1], 16, %2;" \
                 :: "r"(smem), "l"(gptr), "r"(sz) : "memory")

// ============================================================================
// weight pre-convert: W[k][n] fp32 -> oh/ol [n][k] bf16 hi/lo (rn split)
// ============================================================================
__global__ void wconv_kernel(const float* __restrict__ W,
                             __nv_bfloat16* __restrict__ oh,
                             __nv_bfloat16* __restrict__ ol,
                             int K, int Nn)
{
    __shared__ float t[32][33];
    int k0 = blockIdx.y * 32, n0 = blockIdx.x * 32;
    int tx = threadIdx.x, ty = threadIdx.y;
    #pragma unroll
    for (int j = 0; j < 4; j++)
        t[ty + j*8][tx] = W[(size_t)(k0 + ty + j*8) * Nn + n0 + tx];
    __syncthreads();
    #pragma unroll
    for (int j = 0; j < 4; j++) {
        float v = t[tx][ty + j*8];
        __nv_bfloat16 h = __float2bfloat16_rn(v);
        __nv_bfloat16 l = __float2bfloat16_rn(v - __bfloat162float(h));
        size_t o = (size_t)(n0 + ty + j*8) * K + k0 + tx;
        oh[o] = h; ol[o] = l;
    }
}

// ---- pack fp32 activations -> hi/lo bf16 planes (2 elems/thread) ----
__global__ void pack_act(const float* __restrict__ x,
                         __nv_bfloat16* __restrict__ ph,
                         __nv_bfloat16* __restrict__ pl, int n2)
{
    int i = blockIdx.x * blockDim.x + threadIdx.x;
    if (i >= n2) return;
    float2 v = ((const float2*)x)[i];
    ((uint32_t*)ph)[i] = hipair_(v.x, v.y);
    ((uint32_t*)pl)[i] = lopair_(v.x, v.y);
}

// ============================================================================
// bf16x3 GEMM, pre-split operands + cp.async staging.
// C[M,N] = act(A[M,K] @ B[K,N]) over K range [z*kChunk,(z+1)*kChunk).
// A: hi/lo bf16 [m][k]; B: hi/lo bf16 [n][k].
// CTA 128x128, 128 threads, 4 warps of 64x64 (2x2). BK=16, double-buffered.
// SMEM rows: 16 bf16 + 16B pad (48B stride) -> ldmatrix conflict-free.
// PACKO: epilogue also emits hi/lo planes of the (activated) output.
// ============================================================================
template<int MODE, int PACKO>
__global__ void __launch_bounds__(128, 2)
mma_gemm3(float* __restrict__ C,
          __nv_bfloat16* __restrict__ Ph, __nv_bfloat16* __restrict__ Pl,
          const __nv_bfloat16* __restrict__ Ahg, const __nv_bfloat16* __restrict__ Alg,
          const __nv_bfloat16* __restrict__ Bhg, const __nv_bfloat16* __restrict__ Blg,
          int M, int N, int K, int kChunk)
{
    __shared__ __align__(16) uint32_t Ahs[2][128][12];
    __shared__ __align__(16) uint32_t Als[2][128][12];
    __shared__ __align__(16) uint32_t Bhs[2][128][12];
    __shared__ __align__(16) uint32_t Bls[2][128][12];

    const int tid  = threadIdx.x;
    const int lane = tid & 31;
    const int w    = tid >> 5;
    const int row0 = blockIdx.y * 128;
    const int col0 = blockIdx.x * 128;
    const int wm0  = (w >> 1) * 64;
    const int wn0  = (w & 1) * 64;

    const int  kBeg  = blockIdx.z * kChunk;
    const int  nIter = kChunk >> 4;
    const bool a_ok  = (row0 + tid) < M;
    const uint32_t aSz = a_ok ? 16u : 0u;

    // per-thread staging: thread tid owns row tid of all four tiles
    const __nv_bfloat16* Ah_g = Ahg + (size_t)(row0 + (a_ok ? tid : 0)) * K + kBeg;
    const __nv_bfloat16* Al_g = Alg + (size_t)(row0 + (a_ok ? tid : 0)) * K + kBeg;
    const __nv_bfloat16* Bh_g = Bhg + (size_t)(col0 + tid) * K + kBeg;
    const __nv_bfloat16* Bl_g = Blg + (size_t)(col0 + tid) * K + kBeg;

    const uint32_t ahB = (uint32_t)__cvta_generic_to_shared(&Ahs[0][0][0]);
    const uint32_t alB = (uint32_t)__cvta_generic_to_shared(&Als[0][0][0]);
    const uint32_t bhB = (uint32_t)__cvta_generic_to_shared(&Bhs[0][0][0]);
    const uint32_t blB = (uint32_t)__cvta_generic_to_shared(&Bls[0][0][0]);
    const uint32_t rOff = (uint32_t)tid * 48;

    float acc[4][8][4];
    #pragma unroll
    for (int i = 0; i < 4; i++)
        #pragma unroll
        for (int j = 0; j < 8; j++)
            #pragma unroll
            for (int h = 0; h < 4; h++) acc[i][j][h] = 0.0f;

    // stage copies for chunk t into buffer b
    auto stage = [&](int t, int b) {
        const uint32_t bo = (uint32_t)b * 6144 + rOff;
        const int e = t * 16;
        CPA16(ahB + bo,      Ah_g + e,     aSz);
        CPA16(ahB + bo + 16, Ah_g + e + 8, aSz);
        CPA16(alB + bo,      Al_g + e,     aSz);
        CPA16(alB + bo + 16, Al_g + e + 8, aSz);
        CPA16(bhB + bo,      Bh_g + e,     16u);
        CPA16(bhB + bo + 16, Bh_g + e + 8, 16u);
        CPA16(blB + bo,      Bl_g + e,     16u);
        CPA16(blB + bo + 16, Bl_g + e + 8, 16u);
        asm volatile("cp.async.commit_group;" ::: "memory");
    };

    // prologue
    stage(0, 0);
    asm volatile("cp.async.wait_group 0;" ::: "memory");
    __syncthreads();

    // per-lane ldmatrix offsets (within a buffer)
    const uint32_t aOff = (uint32_t)(wm0 + (lane & 15)) * 48 + ((lane >> 4) * 16);
    const uint32_t bOff = (uint32_t)(wn0 + (lane & 7) + ((lane >> 4) & 1) * 8) * 48
                        + (((lane >> 3) & 1) * 16);

    int buf = 0;
    for (int t = 0; t < nIter; t++) {
        if (t + 1 < nIter) stage(t + 1, buf ^ 1);

        const uint32_t bufB = (uint32_t)buf * 6144;
        uint32_t ah[4][4], al[4][4];
        #pragma unroll
        for (int mf = 0; mf < 4; mf++) {
            ldsm4_(ah[mf], ahB + bufB + aOff + mf*768);
            ldsm4_(al[mf], alB + bufB + aOff + mf*768);
        }
        #pragma unroll
        for (int p = 0; p < 4; p++) {
            uint32_t bhr[4], blr[4];
            ldsm4_(bhr, bhB + bufB + bOff + p*768);
            ldsm4_(blr, blB + bufB + bOff + p*768);
            #pragma unroll
            for (int sub = 0; sub < 2; sub++) {
                const int nf = p*2 + sub;
                uint32_t* bh2 = &bhr[sub*2];
                uint32_t* bl2 = &blr[sub*2];
                #pragma unroll
                for (int mf = 0; mf < 4; mf++) {
                    mma_bf16_(acc[mf][nf], ah[mf], bh2);   // hi*hi
                    mma_bf16_(acc[mf][nf], ah[mf], bl2);   // hi*lo
                    mma_bf16_(acc[mf][nf], al[mf], bh2);   // lo*hi
                }
            }
        }

        if (t + 1 < nIter)
            asm volatile("cp.async.wait_group 0;" ::: "memory");
        __syncthreads();
        buf ^= 1;
    }

    // ---- epilogue ----
    float* Cbase = C;
    if (MODE == MODE_PART) Cbase = C + (size_t)blockIdx.z * M * N;

    #pragma unroll
    for (int mf = 0; mf < 4; mf++) {
        const int rbase = row0 + wm0 + mf*16 + (lane >> 2);
        #pragma unroll
        for (int half = 0; half < 2; half++) {
            const int r = rbase + half * 8;
            if (r < M) {
                const int cb = col0 + wn0 + (lane & 3) * 2;
                float* crow = Cbase + (size_t)r * N + cb;
                float u = 0.f, at = 0.f; int bb = 0;
                if (MODE == MODE_WRITE) { u = g_upd[r]; at = g_attn[r]; bb = r >> 8; }
                #pragma unroll
                for (int nf = 0; nf < 8; nf++) {
                    float d0 = acc[mf][nf][half*2 + 0];
                    float d1 = acc[mf][nf][half*2 + 1];
                    if (MODE == MODE_RELU) {
                        d0 = fmaxf(d0, 0.f); d1 = fmaxf(d1, 0.f);
                    } else if (MODE == MODE_WRITE) {
                        const int col = cb + nf*8;
                        float2 lh = *(const float2*)&g_leaf_h[(size_t)r * DD + col];
                        float2 cw = *(const float2*)&g_ctrl_Wh[bb * DD + col];
                        { float cd = sigmoidf_(d0 + cw.x);
                          float wv = u*cd + (1.f-u)*lh.x; d0 = at*wv + (1.f-at)*lh.x; }
                        { float cd = sigmoidf_(d1 + cw.y);
                          float wv = u*cd + (1.f-u)*lh.y; d1 = at*wv + (1.f-at)*lh.y; }
                    }
                    *(float2*)(crow + nf*8) = make_float2(d0, d1);
                    if (PACKO) {
                        size_t po = (size_t)r * N + cb + nf*8;
                        *(uint32_t*)(Ph + po) = hipair_(d0, d1);
                        *(uint32_t*)(Pl + po) = lopair_(d0, d1);
                    }
                }
            }
        }
    }
}

// ============================================================================
// fp32 split-K GEMM (exact; for M=64 GEMMs: ctrl_Wh, LSTM z)
// ============================================================================
template<int MODE>
__global__ void __launch_bounds__(256, 2)
gemm128(float* __restrict__ C, const float* __restrict__ A,
        const float* __restrict__ Bmat, int M, int N, int K, int kChunk)
{
    __shared__ float As[2][16][136];
    __shared__ float Bs[2][16][128];

    const int tid  = threadIdx.x;
    const int row0 = blockIdx.y * 128;
    const int col0 = blockIdx.x * 128;
    const int ty = tid >> 4;
    const int tx = tid & 15;
    const int a_r = tid >> 1;
    const int a_k = (tid & 1) * 8;
    const int b_k = tid >> 4;
    const int b_n = (tid & 15) * 8;

    const int  kBeg  = blockIdx.z * kChunk;
    const int  nIter = kChunk >> 4;
    const bool a_ok  = (row0 + a_r) < M;

    const float* Aptr = A + (size_t)(row0 + a_r) * K + kBeg + a_k;
    const float* Bptr = Bmat + (size_t)(kBeg + b_k) * N + col0 + b_n;

    float acc[8][8];
    #pragma unroll
    for (int i = 0; i < 8; i++)
        #pragma unroll
        for (int j = 0; j < 8; j++) acc[i][j] = 0.0f;

    float a_st[8], b_st[8];
    {
        float4 v0 = make_float4(0,0,0,0), v1 = v0;
        if (a_ok) { v0 = *(const float4*)(Aptr); v1 = *(const float4*)(Aptr + 4); }
        a_st[0]=v0.x; a_st[1]=v0.y; a_st[2]=v0.z; a_st[3]=v0.w;
        a_st[4]=v1.x; a_st[5]=v1.y; a_st[6]=v1.z; a_st[7]=v1.w;
        float4 w0 = *(const float4*)(Bptr);
        float4 w1 = *(const float4*)(Bptr + 4);
        b_st[0]=w0.x; b_st[1]=w0.y; b_st[2]=w0.z; b_st[3]=w0.w;
        b_st[4]=w1.x; b_st[5]=w1.y; b_st[6]=w1.z; b_st[7]=w1.w;
    }
    #pragma unroll
    for (int i = 0; i < 8; i++) As[0][a_k + i][a_r] = a_st[i];
    *(float4*)&Bs[0][b_k][b_n]     = make_float4(b_st[0], b_st[1], b_st[2], b_st[3]);
    *(float4*)&Bs[0][b_k][b_n + 4] = make_float4(b_st[4], b_st[5], b_st[6], b_st[7]);
    __syncthreads();

    int buf = 0;
    for (int t = 0; t < nIter; t++) {
        if (t + 1 < nIter) {
            float4 v0 = make_float4(0,0,0,0), v1 = v0;
            if (a_ok) { v0 = *(const float4*)(Aptr + (t+1)*16);
                        v1 = *(const float4*)(Aptr + (t+1)*16 + 4); }
            a_st[0]=v0.x; a_st[1]=v0.y; a_st[2]=v0.z; a_st[3]=v0.w;
            a_st[4]=v1.x; a_st[5]=v1.y; a_st[6]=v1.z; a_st[7]=v1.w;
            float4 w0 = *(const float4*)(Bptr + (size_t)(t+1)*16*N);
            float4 w1 = *(const float4*)(Bptr + (size_t)(t+1)*16*N + 4);
            b_st[0]=w0.x; b_st[1]=w0.y; b_st[2]=w0.z; b_st[3]=w0.w;
            b_st[4]=w1.x; b_st[5]=w1.y; b_st[6]=w1.z; b_st[7]=w1.w;
        }
        #pragma unroll
        for (int kk = 0; kk < 16; kk++) {
            float a[8], b[8];
            *(float4*)(a)     = *(const float4*)&As[buf][kk][ty*8];
            *(float4*)(a + 4) = *(const float4*)&As[buf][kk][ty*8 + 4];
            *(float4*)(b)     = *(const float4*)&Bs[buf][kk][tx*8];
            *(float4*)(b + 4) = *(const float4*)&Bs[buf][kk][tx*8 + 4];
            #pragma unroll
            for (int i = 0; i < 8; i++)
                #pragma unroll
                for (int j = 0; j < 8; j++)
                    acc[i][j] = fmaf(a[i], b[j], acc[i][j]);
        }
        if (t + 1 < nIter) {
            #pragma unroll
            for (int i = 0; i < 8; i++) As[buf^1][a_k + i][a_r] = a_st[i];
            *(float4*)&Bs[buf^1][b_k][b_n]     = make_float4(b_st[0], b_st[1], b_st[2], b_st[3]);
            *(float4*)&Bs[buf^1][b_k][b_n + 4] = make_float4(b_st[4], b_st[5], b_st[6], b_st[7]);
        }
        __syncthreads();
        buf ^= 1;
    }

    float* Cbase = C;
    if (MODE == MODE_PART) Cbase = C + (size_t)blockIdx.z * M * N;

    #pragma unroll
    for (int i = 0; i < 8; i++) {
        int r = row0 + ty*8 + i;
        if (r < M) {
            float* crow = Cbase + (size_t)r * N + col0 + tx*8;
            #pragma unroll
            for (int h = 0; h < 8; h += 4)
                *(float4*)(crow + h) = make_float4(acc[i][h], acc[i][h+1],
                                                   acc[i][h+2], acc[i][h+3]);
        }
    }
}

// ---- deterministic split-K reduction (+relu, + optional pack) ----
template<int ACT, int PACK>
__global__ void reduce_kernel(float* __restrict__ dst,
                              __nv_bfloat16* __restrict__ ph,
                              __nv_bfloat16* __restrict__ pl,
                              const float* __restrict__ part, int S, int n4)
{
    int i = blockIdx.x * blockDim.x + threadIdx.x;
    if (i >= n4) return;
    const float4* p = (const float4*)part;
    float4 s = p[i];
    for (int k = 1; k < S; k++) {
        float4 v = p[(size_t)k * n4 + i];
        s.x += v.x; s.y += v.y; s.z += v.z; s.w += v.w;
    }
    if (ACT == 1) {
        s.x = fmaxf(s.x, 0.0f); s.y = fmaxf(s.y, 0.0f);
        s.z = fmaxf(s.z, 0.0f); s.w = fmaxf(s.w, 0.0f);
    }
    ((float4*)dst)[i] = s;
    if (PACK) {
        ((uint2*)ph)[i] = make_uint2(hipair_(s.x, s.y), hipair_(s.z, s.w));
        ((uint2*)pl)[i] = make_uint2(lopair_(s.x, s.y), lopair_(s.z, s.w));
    }
}

// ---- per-batch control dot products: ctrl.W_s[512:], ctrl.W_T[512:] ----
__global__ void ctrl_kernel(const float* __restrict__ h0,
                            const float* __restrict__ Ws,
                            const float* __restrict__ WT)
{
    int b = blockIdx.x;
    int lane = threadIdx.x;
    float s1 = 0.0f, s2 = 0.0f;
    for (int u = lane; u < UU; u += 32) {
        float h = h0[b * UU + u];
        s1 += h * Ws[DD + u];
        s2 += h * WT[DD + u];
    }
    #pragma unroll
    for (int o = 16; o; o >>= 1) {
        s1 += __shfl_xor_sync(0xffffffffu, s1, o);
        s2 += __shfl_xor_sync(0xffffffffu, s2, o);
    }
    if (lane == 0) { g_ctrl_s[b] = s1; g_ctrl_T[b] = s2; }
}

// ---- search gates mr for all 255*B internal nodes (warp per node) ----
__global__ void mr_kernel(const float* __restrict__ Ws)
{
    int gw = (blockIdx.x * blockDim.x + threadIdx.x) >> 5;
    int lane = threadIdx.x & 31;
    if (gw >= NROWS_LVL) return;
    const float* row = g_levels + (size_t)gw * DD;
    float s = 0.0f;
    #pragma unroll 4
    for (int k = lane; k < DD; k += 32) s += row[k] * Ws[k];
    #pragma unroll
    for (int o = 16; o; o >>= 1) s += __shfl_xor_sync(0xffffffffu, s, o);
    if (lane == 0) {
        int l = 1;
        #pragma unroll
        for (int i = 2; i <= 8; i++) if (gw >= c_lvl_off[i]) l = i;
        int b = (gw - c_lvl_off[l]) / c_lvl_m[l];
        g_mr[gw] = sigmoidf_(s + g_ctrl_s[b]);
    }
}

// ---- leaf attention: product of 8 path-gate factors ----
__global__ void attn_kernel()
{
    int b = blockIdx.x;
    int leaf = threadIdx.x;
    float a = 1.0f;
    #pragma unroll
    for (int l = 1; l <= 8; l++) {
        int m = NL >> l;
        int j = leaf >> l;
        int c = leaf >> (l - 1);
        float mr = g_mr[c_lvl_off[l] + b * m + j];
        a *= (c & 1) ? mr : (1.0f - mr);
    }
    g_attn[b * NL + leaf] = a;
}

// ---- tree_out[b,e] = sum_n attn[b,n] * inputs[b,n,e] ----
__global__ void treeout_kernel(const float* __restrict__ inputs)
{
    __shared__ float sa[NL];
    int b = blockIdx.x;
    int e = threadIdx.x;
    if (e < NL) sa[e] = g_attn[b * NL + e];
    __syncthreads();
    float s = 0.0f;
    const float* base = inputs + (size_t)b * NL * EE + e;
    #pragma unroll 4
    for (int n = 0; n < NL; n++) s += sa[n] * base[(size_t)n * EE];
    g_tree_out[b * EE + e] = s;
}

// ---- write gate upd per leaf row (warp per row) ----
__global__ void upd_kernel(const float* __restrict__ WT)
{
    int gw = (blockIdx.x * blockDim.x + threadIdx.x) >> 5;
    int lane = threadIdx.x & 31;
    if (gw >= NROWS_LEAF) return;
    const float* row = g_leaf_h + (size_t)gw * DD;
    float s = 0.0f;
    #pragma unroll 4
    for (int k = lane; k < DD; k += 32) s += row[k] * WT[k];
    #pragma unroll
    for (int o = 16; o; o >>= 1) s += __shfl_xor_sync(0xffffffffu, s, o);
    if (lane == 0) g_upd[gw] = sigmoidf_(s + g_ctrl_T[gw >> 8]);
}

// ---- LSTM gates -> h_new, c_new (bias folded in here) ----
__global__ void lstmgate_kernel(const float* __restrict__ c0,
                                const float* __restrict__ bias,
                                float* __restrict__ out_h,
                                float* __restrict__ out_c)
{
    int b = blockIdx.x;
    int u = threadIdx.x;
    float zi = g_z[b * 2048 + u]        + bias[u];
    float zf = g_z[b * 2048 + 512 + u]  + bias[512 + u];
    float zg = g_z[b * 2048 + 1024 + u] + bias[1024 + u];
    float zo = g_z[b * 2048 + 1536 + u] + bias[1536 + u];
    float c = sigmoidf_(zf) * c0[b * UU + u] + sigmoidf_(zi) * tanhf(zg);
    float h = sigmoidf_(zo) * tanhf(c);
    out_h[b * UU + u] = h;
    out_c[b * UU + u] = c;
}

// ============================================================================
extern "C" void kernel_launch(void* const* d_in, const int* in_sizes, int n_in,
                              void* d_out, int out_size)
{
    const float* inputs = (const float*)d_in[0];
    const float* h0     = (const float*)d_in[1];
    const float* c0     = (const float*)d_in[2];
    const float* W_t    = (const float*)d_in[3];
    const float* W_j    = (const float*)d_in[4];
    const float* W_s    = (const float*)d_in[5];
    const float* W_h    = (const float*)d_in[6];
    const float* W_T    = (const float*)d_in[7];
    const float* kern   = (const float*)d_in[8];
    const float* rec    = (const float*)d_in[9];
    const float* bias   = (const float*)d_in[10];

    float* out      = (float*)d_out;
    float* out_h    = out;
    float* out_c    = out + BB * UU;
    float* out_leaf = out + 2 * BB * UU;

    float *p_leaf, *p_levels, *p_part, *p_ctrlWh, *p_z, *p_tree;
    cudaGetSymbolAddress((void**)&p_leaf,   g_leaf_h);
    cudaGetSymbolAddress((void**)&p_levels, g_levels);
    cudaGetSymbolAddress((void**)&p_part,   g_part);
    cudaGetSymbolAddress((void**)&p_ctrlWh, g_ctrl_Wh);
    cudaGetSymbolAddress((void**)&p_z,      g_z);
    cudaGetSymbolAddress((void**)&p_tree,   g_tree_out);

    __nv_bfloat16 *wt_h, *wt_l, *wj_h, *wj_l, *wh_h, *wh_l;
    __nv_bfloat16 *in_h, *in_l, *lf_h, *lf_l, *lv_h, *lv_l;
    cudaGetSymbolAddress((void**)&wt_h, g_wt_h);
    cudaGetSymbolAddress((void**)&wt_l, g_wt_l);
    cudaGetSymbolAddress((void**)&wj_h, g_wj_h);
    cudaGetSymbolAddress((void**)&wj_l, g_wj_l);
    cudaGetSymbolAddress((void**)&wh_h, g_wh_h);
    cudaGetSymbolAddress((void**)&wh_l, g_wh_l);
    cudaGetSymbolAddress((void**)&in_h, g_in_h);
    cudaGetSymbolAddress((void**)&in_l, g_in_l);
    cudaGetSymbolAddress((void**)&lf_h, g_lf_h);
    cudaGetSymbolAddress((void**)&lf_l, g_lf_l);
    cudaGetSymbolAddress((void**)&lv_h, g_lv_h);
    cudaGetSymbolAddress((void**)&lv_l, g_lv_l);

    dim3 blk128(128), blk(256);
    dim3 wblk(32, 8);
    const int lvl_off[10] = {0, 0, 8192, 12288, 14336, 15360, 15872, 16128, 16256, 16320};

    // 0) pre-convert weights + pack inputs
    wconv_kernel<<<dim3(512/32, 512/32),  wblk>>>(W_t, wt_h, wt_l, 512,  512);
    wconv_kernel<<<dim3(512/32, 1024/32), wblk>>>(W_j, wj_h, wj_l, 1024, 512);
    wconv_kernel<<<dim3(512/32, 512/32),  wblk>>>(W_h, wh_h, wh_l, 512,  512);
    pack_act<<<(NROWS_LEAF*EE/2 + 255)/256, 256>>>(inputs, in_h, in_l, NROWS_LEAF*EE/2);

    // 1) leaf embed: relu(inputs @ W_t), emit fp32 + packed planes
    mma_gemm3<MODE_RELU, 1><<<dim3(DD/128, NROWS_LEAF/128, 1), blk128>>>(
        p_leaf, lf_h, lf_l, in_h, in_l, wt_h, wt_l, NROWS_LEAF, DD, EE, EE);

    // 2) join level 1 (M=8192, K=1024): packed leaf pair-rows as A
    mma_gemm3<MODE_RELU, 1><<<dim3(DD/128, (BB*(NL>>1))/128, 1), blk128>>>(
        p_levels, lv_h, lv_l, lf_h, lf_l, wj_h, wj_l, BB*(NL>>1), DD, 2*DD, 2*DD);

    // 3) join levels 2..8: split-K + relu reduce (reduce emits packed planes)
    const int splitS[9] = {0, 1, 2, 4, 8, 16, 16, 32, 32};
    for (int l = 2; l <= 8; l++) {
        int Mrows = BB * (NL >> l);
        int S     = splitS[l];
        int chunk = (2*DD) / S;
        const __nv_bfloat16* ah = lv_h + (size_t)lvl_off[l-1] * DD;
        const __nv_bfloat16* al = lv_l + (size_t)lvl_off[l-1] * DD;
        float* dst = p_levels + (size_t)lvl_off[l] * DD;
        mma_gemm3<MODE_PART, 0><<<dim3(DD/128, (Mrows + 127)/128, S), blk128>>>(
            p_part, (__nv_bfloat16*)0, (__nv_bfloat16*)0,
            ah, al, wj_h, wj_l, Mrows, DD, 2*DD, chunk);
        int n4 = (Mrows * DD) / 4;
        reduce_kernel<1, 1><<<(n4 + 255)/256, 256>>>(
            dst, lv_h + (size_t)lvl_off[l] * DD, lv_l + (size_t)lvl_off[l] * DD,
            p_part, S, n4);
    }

    // 4) per-batch control terms; ctrl_Wh = h0 @ W_h[512:,:] (EXACT fp32 split-K)
    ctrl_kernel<<<BB, 32>>>(h0, W_s, W_T);
    gemm128<MODE_PART><<<dim3(DD/128, 1, 8), blk>>>(
        p_part, h0, W_h + DD*DD, BB, DD, UU, UU/8);
    reduce_kernel<0, 0><<<(BB*DD/4 + 255)/256, 256>>>(
        p_ctrlWh, (__nv_bfloat16*)0, (__nv_bfloat16*)0, p_part, 8, BB*DD/4);

    // 5) search gates, attentions, retrieval, write gates
    mr_kernel<<<(NROWS_LVL * 32 + 255)/256, 256>>>(W_s);
    attn_kernel<<<BB, NL>>>();
    treeout_kernel<<<BB, EE>>>(inputs);
    upd_kernel<<<(NROWS_LEAF * 32 + 255)/256, 256>>>(W_T);

    // 6) fused write-update GEMM straight into d_out
    mma_gemm3<MODE_WRITE, 0><<<dim3(DD/128, NROWS_LEAF/128, 1), blk128>>>(
        out_leaf, (__nv_bfloat16*)0, (__nv_bfloat16*)0,
        lf_h, lf_l, wh_h, wh_l, NROWS_LEAF, DD, DD, DD);

    // 7) LSTM z (EXACT fp32 split-K): tree_out@kernel -> parts 0..7,
    //    h0@rec_kernel -> parts 8..15, reduce S=16, then gates (+bias)
    gemm128<MODE_PART><<<dim3(4*UU/128, 1, 8), blk>>>(
        p_part, p_tree, kern, BB, 4*UU, EE, EE/8);
    gemm128<MODE_PART><<<dim3(4*UU/128, 1, 8), blk>>>(
        p_part + (size_t)8 * BB * 4*UU, h0, rec, BB, 4*UU, UU, UU/8);
    reduce_kernel<0, 0><<<(BB*4*UU/4 + 255)/256, 256>>>(
        p_z, (__nv_bfloat16*)0, (__nv_bfloat16*)0, p_part, 16, BB*4*UU/4);
    lstmgate_kernel<<<BB, UU>>>(c0, bias, out_h, out_c);
}